// round 2
// baseline (speedup 1.0000x reference)
#include <cuda_runtime.h>
#include <cuda_bf16.h>
#include <stdint.h>

// ---------------------------------------------------------------------------
// GCN 2-layer forward:
//   deg = 1 + indeg(dst);  dinv = deg^-0.5
//   h1  = x @ W1
//   a1[i] = b1 + h1[i]*dinv[i]^2 + sum_{e:dst=i} h1[src]*dinv[src]*dinv[i]
//   h2  = a1 @ W2
//   out[i] = b2 + h2[i]*dinv[i]^2 + sum_{e:dst=i} h2[src]*dinv[src]*dinv[i]
// Edge index dtype (int32 vs int64) is auto-detected on device.
// ---------------------------------------------------------------------------

#define MAXN 100000
#define MAXF 512

__device__ float g_dinv[MAXN];
__device__ float g_h[(size_t)MAXN * MAXF];
__device__ float g_agg[(size_t)MAXN * MAXF];
__device__ int   g_is64;

// ---------------------------------------------------------------------------
// edge index accessor (flag-dispatched)
// ---------------------------------------------------------------------------
__device__ __forceinline__ long long edge_at(const void* ei, long long idx, int is64) {
    if (is64) return ((const long long*)ei)[idx];
    return (long long)((const int*)ei)[idx];
}

// Detect int32 vs int64: read first 64 values as int64; true int64 indices are
// in [0, n). For int32 data, the high 32 bits come from the next index (>=1
// with overwhelming probability), pushing the value far outside [0, n).
__global__ void k_detect(const void* ei, long long nelem, int n) {
    if (threadIdx.x != 0 || blockIdx.x != 0) return;
    const long long* p = (const long long*)ei;
    long long m = 64;
    if (m > nelem / 2) m = nelem / 2;  // safe even if data is int32 (nelem*4 bytes)
    int is64 = 1;
    for (long long i = 0; i < m; i++) {
        long long v = p[i];
        if (v < 0 || v >= (long long)n) { is64 = 0; break; }
    }
    g_is64 = is64;
}

// ---------------------------------------------------------------------------
// degree / dinv
// ---------------------------------------------------------------------------
__global__ void k_init_deg(float* deg, int n) {
    int i = blockIdx.x * blockDim.x + threadIdx.x;
    if (i < n) deg[i] = 1.0f;  // self loop
}

__global__ void k_count_deg(const void* __restrict__ ei, long long E, float* deg) {
    long long i = (long long)blockIdx.x * blockDim.x + threadIdx.x;
    if (i >= E) return;
    int is64 = g_is64;
    long long d = edge_at(ei, E + i, is64);  // dst = second half
    atomicAdd(&deg[d], 1.0f);
}

__global__ void k_finalize_dinv(float* deg, int n) {
    int i = blockIdx.x * blockDim.x + threadIdx.x;
    if (i < n) deg[i] = rsqrtf(deg[i]);
}

// ---------------------------------------------------------------------------
// SGEMM: C[M,N] = A[M,K] @ B[K,N]
// BM=BN=128, BK=8, 256 threads, 8x8 micro-tile per thread.
// Requires N % 128 == 0, K % 8 == 0. M guarded.
// ---------------------------------------------------------------------------
__global__ __launch_bounds__(256)
void k_gemm128(const float* __restrict__ A, const float* __restrict__ B,
               float* __restrict__ C, int M, int N, int K) {
    __shared__ float As[8][129];   // transposed: As[k][m]
    __shared__ float Bs[8][128];

    const int t  = threadIdx.x;
    const int m0 = blockIdx.y * 128;
    const int n0 = blockIdx.x * 128;
    const int tx = t & 15;   // 0..15 -> N
    const int ty = t >> 4;   // 0..15 -> M

    const int arow = t >> 1;          // 0..127
    const int acol = (t & 1) * 4;     // 0 or 4
    const int brow = t >> 5;          // 0..7
    const int bcol = (t & 31) * 4;    // 0..124

    float acc[8][8];
#pragma unroll
    for (int i = 0; i < 8; i++)
#pragma unroll
        for (int j = 0; j < 8; j++) acc[i][j] = 0.0f;

    for (int k0 = 0; k0 < K; k0 += 8) {
        float4 a4;
        if (m0 + arow < M) {
            a4 = *(const float4*)&A[(size_t)(m0 + arow) * K + k0 + acol];
        } else {
            a4 = make_float4(0.f, 0.f, 0.f, 0.f);
        }
        As[acol + 0][arow] = a4.x;
        As[acol + 1][arow] = a4.y;
        As[acol + 2][arow] = a4.z;
        As[acol + 3][arow] = a4.w;

        float4 b4 = *(const float4*)&B[(size_t)(k0 + brow) * N + n0 + bcol];
        *(float4*)&Bs[brow][bcol] = b4;

        __syncthreads();

#pragma unroll
        for (int k = 0; k < 8; ++k) {
            float ra[8], rb[8];
#pragma unroll
            for (int i = 0; i < 8; i++) ra[i] = As[k][ty * 8 + i];
#pragma unroll
            for (int j = 0; j < 8; j++) rb[j] = Bs[k][tx * 8 + j];
#pragma unroll
            for (int i = 0; i < 8; i++)
#pragma unroll
                for (int j = 0; j < 8; j++) acc[i][j] += ra[i] * rb[j];
        }
        __syncthreads();
    }

#pragma unroll
    for (int i = 0; i < 8; i++) {
        int r = m0 + ty * 8 + i;
        if (r < M) {
#pragma unroll
            for (int j = 0; j < 8; j += 4) {
                float4 v = make_float4(acc[i][j], acc[i][j + 1], acc[i][j + 2], acc[i][j + 3]);
                *(float4*)&C[(size_t)r * N + n0 + tx * 8 + j] = v;
            }
        }
    }
}

// ---------------------------------------------------------------------------
// out[i] = b + h[i] * dinv[i]^2   (bias + self-loop contribution)
// ---------------------------------------------------------------------------
template <int F4>
__global__ void k_agg_init(const float* __restrict__ h, const float* __restrict__ b,
                           const float* __restrict__ dinv, float* __restrict__ out,
                           long long total /* = n*F4 */) {
    long long idx = (long long)blockIdx.x * blockDim.x + threadIdx.x;
    if (idx >= total) return;
    int i  = (int)(idx / F4);
    int f4 = (int)(idx % F4);
    float di = dinv[i];
    float s  = di * di;
    float4 v  = ((const float4*)h)[idx];
    float4 bb = ((const float4*)b)[f4];
    float4 o  = make_float4(bb.x + v.x * s, bb.y + v.y * s, bb.z + v.z * s, bb.w + v.w * s);
    ((float4*)out)[idx] = o;
}

// ---------------------------------------------------------------------------
// edge aggregation: out[dst] += h[src] * dinv[src]*dinv[dst]
// one float4 of features per thread; consecutive threads cover one edge's row.
// ---------------------------------------------------------------------------
template <int F4>
__global__ void k_agg_edges(const void* __restrict__ ei, long long E,
                            const float* __restrict__ dinv, const float* __restrict__ h,
                            float* __restrict__ out, long long total /* = E*F4 */) {
    long long idx = (long long)blockIdx.x * blockDim.x + threadIdx.x;
    if (idx >= total) return;
    long long e = idx / F4;
    int f4      = (int)(idx % F4);
    int is64    = g_is64;
    long long s = edge_at(ei, e, is64);
    long long d = edge_at(ei, E + e, is64);
    float norm  = __ldg(&dinv[s]) * __ldg(&dinv[d]);
    float4 v    = ((const float4*)h)[(size_t)s * F4 + f4];
    float* o    = out + ((size_t)d * F4 + f4) * 4;
    atomicAdd(o + 0, v.x * norm);
    atomicAdd(o + 1, v.y * norm);
    atomicAdd(o + 2, v.z * norm);
    atomicAdd(o + 3, v.w * norm);
}

// ---------------------------------------------------------------------------
// launch
// ---------------------------------------------------------------------------
extern "C" void kernel_launch(void* const* d_in, const int* in_sizes, int n_in,
                              void* d_out, int out_size) {
    const float* x   = (const float*)d_in[0];
    const void*  ei  = d_in[1];
    // d_in[2] = original_size (unused; == n here)
    const float* W1  = (const float*)d_in[3];
    const float* b1  = (const float*)d_in[4];
    const float* W2  = (const float*)d_in[5];
    const float* b2  = (const float*)d_in[6];
    float*       out = (float*)d_out;

    const long long nelem = (long long)in_sizes[1];  // 2*E (element count, dtype-independent)
    const long long E     = nelem / 2;
    const int dhid        = in_sizes[4];             // 512
    const int dout        = in_sizes[6];             // 128
    const int din         = in_sizes[3] / dhid;      // 512
    const int n           = in_sizes[0] / din;       // 100000

    float *dinv_p, *h_p, *agg_p;
    cudaGetSymbolAddress((void**)&dinv_p, g_dinv);
    cudaGetSymbolAddress((void**)&h_p,    g_h);
    cudaGetSymbolAddress((void**)&agg_p,  g_agg);

    // --- dtype detect + degree / dinv ---
    k_detect<<<1, 32>>>(ei, nelem, n);
    k_init_deg<<<(n + 255) / 256, 256>>>(dinv_p, n);
    k_count_deg<<<(int)((E + 255) / 256), 256>>>(ei, E, dinv_p);
    k_finalize_dinv<<<(n + 255) / 256, 256>>>(dinv_p, n);

    // --- layer 1: h = x @ W1 ; aggregate ---
    {
        dim3 grid(dhid / 128, (n + 127) / 128);
        k_gemm128<<<grid, 256>>>(x, W1, h_p, n, dhid, din);

        const int F4 = 512 / 4;
        long long tot_init = (long long)n * F4;
        k_agg_init<128><<<(int)((tot_init + 255) / 256), 256>>>(h_p, b1, dinv_p, agg_p, tot_init);
        long long tot_edge = E * F4;
        k_agg_edges<128><<<(int)((tot_edge + 255) / 256), 256>>>(ei, E, dinv_p, h_p, agg_p, tot_edge);
    }

    // --- layer 2: h2 = agg @ W2 ; aggregate into d_out ---
    {
        dim3 grid(dout / 128, (n + 127) / 128);
        k_gemm128<<<grid, 256>>>(agg_p, W2, h_p, n, dout, dhid);

        const int F4 = 128 / 4;
        long long tot_init = (long long)n * F4;
        k_agg_init<32><<<(int)((tot_init + 255) / 256), 256>>>(h_p, b2, dinv_p, out, tot_init);
        long long tot_edge = E * F4;
        k_agg_edges<32><<<(int)((tot_edge + 255) / 256), 256>>>(ei, E, dinv_p, h_p, out, tot_edge);
    }

    (void)n_in; (void)out_size;
}

// round 3
// speedup vs baseline: 3.6958x; 3.6958x over previous
#include <cuda_runtime.h>
#include <cuda_bf16.h>
#include <stdint.h>

// ---------------------------------------------------------------------------
// GCN 2-layer, CSR pull-based aggregation + tf32 tensor-core GEMM.
//   dinv = (1 + indeg)^-1/2
//   hs1  = (x @ W1) * dinv[row]                 (GEMM epilogue scaling)
//   a1[i]= b1 + dinv[i] * (hs1[i] + sum_{e: dst=i} hs1[src])   (pull)
//   hs2  = (a1 @ W2) * dinv[row]
//   out[i]= b2 + dinv[i] * (hs2[i] + sum hs2[src])
// Edge index dtype (int32 vs int64) auto-detected on device.
// ---------------------------------------------------------------------------

#define MAXN 100352
#define MAXE 1048576
#define MAXF 512

__device__ float g_dinv[MAXN];
__device__ float g_h[(size_t)MAXN * MAXF];     // GEMM output (dinv-scaled)
__device__ float g_agg[(size_t)MAXN * MAXF];   // layer-1 aggregated output
__device__ int   g_cnt[MAXN];
__device__ int   g_rowp[MAXN + 1];
__device__ int   g_cur[MAXN];
__device__ int   g_col[MAXE];
__device__ int   g_is64;

// ---------------------------------------------------------------------------
__device__ __forceinline__ long long edge_at(const void* ei, long long idx, int is64) {
    if (is64) return ((const long long*)ei)[idx];
    return (long long)((const int*)ei)[idx];
}

__global__ void k_detect(const void* ei, long long nelem, int n) {
    if (threadIdx.x != 0 || blockIdx.x != 0) return;
    const long long* p = (const long long*)ei;
    long long m = 64;
    if (m > nelem / 2) m = nelem / 2;
    int is64 = 1;
    for (long long i = 0; i < m; i++) {
        long long v = p[i];
        if (v < 0 || v >= (long long)n) { is64 = 0; break; }
    }
    g_is64 = is64;
}

__global__ void k_zero_cnt(int* cnt, int n) {
    int i = blockIdx.x * blockDim.x + threadIdx.x;
    if (i < n) cnt[i] = 0;
}

__global__ void k_hist(const void* __restrict__ ei, long long E, int* __restrict__ cnt) {
    long long i = (long long)blockIdx.x * blockDim.x + threadIdx.x;
    if (i >= E) return;
    int d = (int)edge_at(ei, E + i, g_is64);
    atomicAdd(&cnt[d], 1);
}

// single-block sequential-chunk exclusive scan, writes rowp[0..n]
__global__ void k_scan(const int* __restrict__ cnt, int* __restrict__ rowp, int n) {
    __shared__ int warpsum[32];
    __shared__ int s_carry;
    const int t = threadIdx.x;       // 1024 threads
    const int lane = t & 31, w = t >> 5;
    if (t == 0) s_carry = 0;
    __syncthreads();
    for (int base = 0; base < n; base += 1024) {
        int i = base + t;
        int v = (i < n) ? cnt[i] : 0;
        int x = v;
#pragma unroll
        for (int off = 1; off < 32; off <<= 1) {
            int y = __shfl_up_sync(0xFFFFFFFFu, x, off);
            if (lane >= off) x += y;
        }
        if (lane == 31) warpsum[w] = x;
        __syncthreads();
        if (w == 0) {
            int s = warpsum[lane];
#pragma unroll
            for (int off = 1; off < 32; off <<= 1) {
                int y = __shfl_up_sync(0xFFFFFFFFu, s, off);
                if (lane >= off) s += y;
            }
            warpsum[lane] = s;
        }
        __syncthreads();
        int wpre = (w > 0) ? warpsum[w - 1] : 0;
        if (i < n) rowp[i] = x - v + wpre + s_carry;
        __syncthreads();
        if (t == 0) s_carry += warpsum[31];
        __syncthreads();
    }
    if (t == 0) rowp[n] = s_carry;
}

__global__ void k_dinv_cursor(const int* __restrict__ cnt, const int* __restrict__ rowp,
                              float* __restrict__ dinv, int* __restrict__ cur, int n) {
    int i = blockIdx.x * blockDim.x + threadIdx.x;
    if (i >= n) return;
    dinv[i] = rsqrtf((float)cnt[i] + 1.0f);
    cur[i]  = rowp[i];
}

__global__ void k_scatter(const void* __restrict__ ei, long long E,
                          int* __restrict__ cur, int* __restrict__ colA) {
    long long i = (long long)blockIdx.x * blockDim.x + threadIdx.x;
    if (i >= E) return;
    int is64 = g_is64;
    int s = (int)edge_at(ei, i, is64);
    int d = (int)edge_at(ei, E + i, is64);
    int pos = atomicAdd(&cur[d], 1);
    colA[pos] = s;
}

// ---------------------------------------------------------------------------
// tf32 tensor-core GEMM: Hs[M,N] = (A[M,K] @ B[K,N]) * dinv[row]
// BM=BN=128, BK=16, 256 threads (8 warps: 4x2), warp tile 32x64,
// mma.m16n8k8 tf32, register-staged double-buffered smem.
// Requires N % 128 == 0, K % 16 == 0. M guarded.
// ---------------------------------------------------------------------------
__device__ __forceinline__ uint32_t f2tf(float x) {
    uint32_t u;
    asm("cvt.rna.tf32.f32 %0, %1;" : "=r"(u) : "f"(x));
    return u;
}

__global__ __launch_bounds__(256, 2)
void k_gemm_tf32(const float* __restrict__ A, const float* __restrict__ B,
                 const float* __restrict__ dinv, float* __restrict__ Hs,
                 int M, int N, int K)
{
    __shared__ uint32_t As[2][16][136];   // [k][m], stride 136 -> conflict-free frags
    __shared__ uint32_t Bs[2][16][136];   // [k][n]

    const int t    = threadIdx.x;
    const int lane = t & 31;
    const int wid  = t >> 5;
    const int wm   = wid >> 1;        // 0..3 (32 rows each)
    const int wn   = wid & 1;         // 0..1 (64 cols each)
    const int g    = lane >> 2;       // 0..7
    const int c    = lane & 3;        // 0..3
    const int m0   = blockIdx.y * 128;
    const int n0   = blockIdx.x * 128;

    const int arow = t >> 2;          // 0..63 (it adds 64)
    const int ac4  = t & 3;
    const int bkr  = t >> 5;          // 0..7 (it adds 8)
    const int bn4  = t & 31;

    float acc[2][8][4];
#pragma unroll
    for (int i = 0; i < 2; i++)
#pragma unroll
        for (int j = 0; j < 8; j++)
#pragma unroll
            for (int q = 0; q < 4; q++) acc[i][j][q] = 0.0f;

    const int nt = K / 16;
    float4 ra[2], rb[2];

    // prologue: load tile 0 into regs
#pragma unroll
    for (int it = 0; it < 2; it++) {
        int row = arow + it * 64;
        ra[it] = (m0 + row < M) ? *(const float4*)&A[(size_t)(m0 + row) * K + ac4 * 4]
                                : make_float4(0.f, 0.f, 0.f, 0.f);
        rb[it] = *(const float4*)&B[(size_t)(bkr + it * 8) * N + n0 + bn4 * 4];
    }
    // store tile 0 into smem buf 0
#pragma unroll
    for (int it = 0; it < 2; it++) {
        int row = arow + it * 64;
        As[0][ac4 * 4 + 0][row] = f2tf(ra[it].x);
        As[0][ac4 * 4 + 1][row] = f2tf(ra[it].y);
        As[0][ac4 * 4 + 2][row] = f2tf(ra[it].z);
        As[0][ac4 * 4 + 3][row] = f2tf(ra[it].w);
        int kr = bkr + it * 8;
        Bs[0][kr][bn4 * 4 + 0] = f2tf(rb[it].x);
        Bs[0][kr][bn4 * 4 + 1] = f2tf(rb[it].y);
        Bs[0][kr][bn4 * 4 + 2] = f2tf(rb[it].z);
        Bs[0][kr][bn4 * 4 + 3] = f2tf(rb[it].w);
    }

    for (int tt = 0; tt < nt; tt++) {
        __syncthreads();
        const int buf = tt & 1;

        if (tt + 1 < nt) {
            int k0 = (tt + 1) * 16;
#pragma unroll
            for (int it = 0; it < 2; it++) {
                int row = arow + it * 64;
                ra[it] = (m0 + row < M) ? *(const float4*)&A[(size_t)(m0 + row) * K + k0 + ac4 * 4]
                                        : make_float4(0.f, 0.f, 0.f, 0.f);
                rb[it] = *(const float4*)&B[(size_t)(k0 + bkr + it * 8) * N + n0 + bn4 * 4];
            }
        }

        // compute on buf
#pragma unroll
        for (int kk = 0; kk < 2; kk++) {
            uint32_t af[2][4];
            uint32_t bf[8][2];
            const int kb = kk * 8;
#pragma unroll
            for (int fm = 0; fm < 2; fm++) {
                int mm = wm * 32 + fm * 16 + g;
                af[fm][0] = As[buf][kb + c][mm];
                af[fm][1] = As[buf][kb + c][mm + 8];
                af[fm][2] = As[buf][kb + c + 4][mm];
                af[fm][3] = As[buf][kb + c + 4][mm + 8];
            }
#pragma unroll
            for (int fn = 0; fn < 8; fn++) {
                int nn = wn * 64 + fn * 8 + g;
                bf[fn][0] = Bs[buf][kb + c][nn];
                bf[fn][1] = Bs[buf][kb + c + 4][nn];
            }
#pragma unroll
            for (int fm = 0; fm < 2; fm++)
#pragma unroll
                for (int fn = 0; fn < 8; fn++) {
                    asm volatile(
                        "mma.sync.aligned.m16n8k8.row.col.f32.tf32.tf32.f32 "
                        "{%0,%1,%2,%3}, {%4,%5,%6,%7}, {%8,%9}, {%0,%1,%2,%3};"
                        : "+f"(acc[fm][fn][0]), "+f"(acc[fm][fn][1]),
                          "+f"(acc[fm][fn][2]), "+f"(acc[fm][fn][3])
                        : "r"(af[fm][0]), "r"(af[fm][1]), "r"(af[fm][2]), "r"(af[fm][3]),
                          "r"(bf[fn][0]), "r"(bf[fn][1]));
                }
        }

        if (tt + 1 < nt) {
            const int nbuf = 1 - buf;
#pragma unroll
            for (int it = 0; it < 2; it++) {
                int row = arow + it * 64;
                As[nbuf][ac4 * 4 + 0][row] = f2tf(ra[it].x);
                As[nbuf][ac4 * 4 + 1][row] = f2tf(ra[it].y);
                As[nbuf][ac4 * 4 + 2][row] = f2tf(ra[it].z);
                As[nbuf][ac4 * 4 + 3][row] = f2tf(ra[it].w);
                int kr = bkr + it * 8;
                Bs[nbuf][kr][bn4 * 4 + 0] = f2tf(rb[it].x);
                Bs[nbuf][kr][bn4 * 4 + 1] = f2tf(rb[it].y);
                Bs[nbuf][kr][bn4 * 4 + 2] = f2tf(rb[it].z);
                Bs[nbuf][kr][bn4 * 4 + 3] = f2tf(rb[it].w);
            }
        }
    }

    // epilogue: scale rows by dinv, store
#pragma unroll
    for (int fm = 0; fm < 2; fm++) {
        int r0 = m0 + wm * 32 + fm * 16 + g;
        int r1 = r0 + 8;
        float d0 = (r0 < M) ? dinv[r0] : 0.0f;
        float d1 = (r1 < M) ? dinv[r1] : 0.0f;
#pragma unroll
        for (int fn = 0; fn < 8; fn++) {
            int col = n0 + wn * 64 + fn * 8 + c * 2;
            if (r0 < M) {
                float2 v = make_float2(acc[fm][fn][0] * d0, acc[fm][fn][1] * d0);
                *(float2*)&Hs[(size_t)r0 * N + col] = v;
            }
            if (r1 < M) {
                float2 v = make_float2(acc[fm][fn][2] * d1, acc[fm][fn][3] * d1);
                *(float2*)&Hs[(size_t)r1 * N + col] = v;
            }
        }
    }
}

// ---------------------------------------------------------------------------
// pull aggregation: out[i] = b + dinv[i] * (hs[i] + sum_{e in CSR row i} hs[col[e]])
// thread = (dst, f4). F4 >= 32 -> whole warp shares dst (uniform loop, bcast col).
// ---------------------------------------------------------------------------
template <int F4>
__global__ void k_pull(const int* __restrict__ rowp, const int* __restrict__ colA,
                       const float* __restrict__ hs, const float* __restrict__ dinv,
                       const float* __restrict__ bias, float* __restrict__ out, int n) {
    int idx = blockIdx.x * blockDim.x + threadIdx.x;
    int dst = idx / F4;
    int f4  = idx % F4;
    if (dst >= n) return;
    const float4* h4 = (const float4*)hs;
    float4 acc = h4[(size_t)dst * F4 + f4];   // self loop (hs already *dinv[src])
    int e0 = __ldg(&rowp[dst]);
    int e1 = __ldg(&rowp[dst + 1]);
    for (int e = e0; e < e1; e++) {
        int s = __ldg(&colA[e]);
        float4 v = h4[(size_t)s * F4 + f4];
        acc.x += v.x; acc.y += v.y; acc.z += v.z; acc.w += v.w;
    }
    float d = dinv[dst];
    float4 bb = ((const float4*)bias)[f4];
    float4 o = make_float4(bb.x + acc.x * d, bb.y + acc.y * d,
                           bb.z + acc.z * d, bb.w + acc.w * d);
    ((float4*)out)[idx] = o;
}

// ---------------------------------------------------------------------------
extern "C" void kernel_launch(void* const* d_in, const int* in_sizes, int n_in,
                              void* d_out, int out_size) {
    const float* x   = (const float*)d_in[0];
    const void*  ei  = d_in[1];
    const float* W1  = (const float*)d_in[3];
    const float* b1  = (const float*)d_in[4];
    const float* W2  = (const float*)d_in[5];
    const float* b2  = (const float*)d_in[6];
    float*       out = (float*)d_out;

    const long long nelem = (long long)in_sizes[1];
    const long long E     = nelem / 2;
    const int dhid        = in_sizes[4];         // 512
    const int dout        = in_sizes[6];         // 128
    const int din         = in_sizes[3] / dhid;  // 512
    const int n           = in_sizes[0] / din;   // 100000

    float *dinv_p, *h_p, *agg_p;
    int *cnt_p, *rowp_p, *cur_p, *col_p;
    cudaGetSymbolAddress((void**)&dinv_p, g_dinv);
    cudaGetSymbolAddress((void**)&h_p,    g_h);
    cudaGetSymbolAddress((void**)&agg_p,  g_agg);
    cudaGetSymbolAddress((void**)&cnt_p,  g_cnt);
    cudaGetSymbolAddress((void**)&rowp_p, g_rowp);
    cudaGetSymbolAddress((void**)&cur_p,  g_cur);
    cudaGetSymbolAddress((void**)&col_p,  g_col);

    const int eb = (int)((E + 255) / 256);
    const int nb = (n + 255) / 256;

    // --- CSR build + dinv ---
    k_detect<<<1, 32>>>(ei, nelem, n);
    k_zero_cnt<<<nb, 256>>>(cnt_p, n);
    k_hist<<<eb, 256>>>(ei, E, cnt_p);
    k_scan<<<1, 1024>>>(cnt_p, rowp_p, n);
    k_dinv_cursor<<<nb, 256>>>(cnt_p, rowp_p, dinv_p, cur_p, n);
    k_scatter<<<eb, 256>>>(ei, E, cur_p, col_p);

    // --- layer 1 ---
    {
        dim3 grid(dhid / 128, (n + 127) / 128);
        k_gemm_tf32<<<grid, 256>>>(x, W1, dinv_p, h_p, n, dhid, din);
        int tot = n * (dhid / 4);
        k_pull<128><<<(tot + 255) / 256, 256>>>(rowp_p, col_p, h_p, dinv_p, b1, agg_p, n);
    }

    // --- layer 2 ---
    {
        dim3 grid(dout / 128, (n + 127) / 128);
        k_gemm_tf32<<<grid, 256>>>(agg_p, W2, dinv_p, h_p, n, dout, dhid);
        int tot = n * (dout / 4);
        k_pull<32><<<(tot + 255) / 256, 256>>>(rowp_p, col_p, h_p, dinv_p, b2, out, n);
    }

    (void)n_in; (void)out_size;
}

// round 4
// speedup vs baseline: 4.3290x; 1.1713x over previous
#include <cuda_runtime.h>
#include <cuda_bf16.h>
#include <stdint.h>

// ---------------------------------------------------------------------------
// GCN 2-layer, CSR pull-based aggregation + tf32 tensor-core GEMMs.
//   dinv = (1 + indeg)^-1/2
//   hs1  = (x @ W1) * dinv[row]                  (GEMM1 epilogue scaling)
//   a1[i]= b1 + dinv[i] * (hs1[i] + sum_{e: dst=i} hs1[src])   (pull, L2-chunked)
//   hs2  = (a1 @ W2) * dinv[row]
//   out[i]= b2 + dinv[i] * (hs2[i] + sum hs2[src])
// ---------------------------------------------------------------------------

#define MAXN 100352
#define MAXE 1048576
#define MAXF 512

__device__ float g_dinv[MAXN];
__device__ float g_h[(size_t)MAXN * MAXF];
__device__ float g_agg[(size_t)MAXN * MAXF];
__device__ int   g_cnt[MAXN];
__device__ int   g_rowp[MAXN + 1];
__device__ int   g_cur[MAXN];
__device__ int   g_col[MAXE];
__device__ int   g_bsum[1025];
__device__ int   g_is64;

// ---------------------------------------------------------------------------
__device__ __forceinline__ long long edge_at(const void* ei, long long idx, int is64) {
    if (is64) return ((const long long*)ei)[idx];
    return (long long)((const int*)ei)[idx];
}

__global__ void k_detect(const void* ei, long long nelem, int n) {
    if (threadIdx.x != 0 || blockIdx.x != 0) return;
    const long long* p = (const long long*)ei;
    long long m = 64;
    if (m > nelem / 2) m = nelem / 2;
    int is64 = 1;
    for (long long i = 0; i < m; i++) {
        long long v = p[i];
        if (v < 0 || v >= (long long)n) { is64 = 0; break; }
    }
    g_is64 = is64;
}

__global__ void k_zero_cnt(int* cnt, int n) {
    int i = blockIdx.x * blockDim.x + threadIdx.x;
    if (i < n) cnt[i] = 0;
}

__global__ void k_hist(const void* __restrict__ ei, long long E, int* __restrict__ cnt) {
    long long i = (long long)blockIdx.x * blockDim.x + threadIdx.x;
    if (i >= E) return;
    int d = (int)edge_at(ei, E + i, g_is64);
    atomicAdd(&cnt[d], 1);
}

// -------- multi-block exclusive scan --------
__global__ void k_scan_blk(const int* __restrict__ cnt, int* __restrict__ rowp,
                           int* __restrict__ bsum, int n) {
    __shared__ int warpsum[32];
    const int t = threadIdx.x;                 // 1024
    const int lane = t & 31, w = t >> 5;
    int i = blockIdx.x * 1024 + t;
    int v = (i < n) ? cnt[i] : 0;
    int x = v;
#pragma unroll
    for (int off = 1; off < 32; off <<= 1) {
        int y = __shfl_up_sync(0xFFFFFFFFu, x, off);
        if (lane >= off) x += y;
    }
    if (lane == 31) warpsum[w] = x;
    __syncthreads();
    if (w == 0) {
        int s = warpsum[lane];
#pragma unroll
        for (int off = 1; off < 32; off <<= 1) {
            int y = __shfl_up_sync(0xFFFFFFFFu, s, off);
            if (lane >= off) s += y;
        }
        warpsum[lane] = s;
    }
    __syncthreads();
    int wpre = (w > 0) ? warpsum[w - 1] : 0;
    if (i < n) rowp[i] = x - v + wpre;
    if (t == 1023) bsum[blockIdx.x] = wpre + x;  // block total
}

__global__ void k_scan_top(int* __restrict__ bsum, int nb) {
    __shared__ int warpsum[32];
    const int t = threadIdx.x;                 // 1024 (nb <= 1024)
    const int lane = t & 31, w = t >> 5;
    int v = (t < nb) ? bsum[t] : 0;
    int x = v;
#pragma unroll
    for (int off = 1; off < 32; off <<= 1) {
        int y = __shfl_up_sync(0xFFFFFFFFu, x, off);
        if (lane >= off) x += y;
    }
    if (lane == 31) warpsum[w] = x;
    __syncthreads();
    if (w == 0) {
        int s = warpsum[lane];
#pragma unroll
        for (int off = 1; off < 32; off <<= 1) {
            int y = __shfl_up_sync(0xFFFFFFFFu, s, off);
            if (lane >= off) s += y;
        }
        warpsum[lane] = s;
    }
    __syncthreads();
    int wpre = (w > 0) ? warpsum[w - 1] : 0;
    if (t < nb) bsum[t] = x - v + wpre;         // exclusive
    if (t == 1023) bsum[nb] = warpsum[31];      // grand total
}

__global__ void k_scan_add(int* __restrict__ rowp, const int* __restrict__ bsum,
                           int n, int nb) {
    int i = blockIdx.x * blockDim.x + threadIdx.x;
    if (i < n) rowp[i] += bsum[i >> 10];
    if (i == n) rowp[n] = bsum[nb];
}

__global__ void k_dinv_cursor(const int* __restrict__ cnt, const int* __restrict__ rowp,
                              float* __restrict__ dinv, int* __restrict__ cur, int n) {
    int i = blockIdx.x * blockDim.x + threadIdx.x;
    if (i >= n) return;
    dinv[i] = rsqrtf((float)cnt[i] + 1.0f);
    cur[i]  = rowp[i];
}

__global__ void k_scatter(const void* __restrict__ ei, long long E,
                          int* __restrict__ cur, int* __restrict__ colA) {
    long long i = (long long)blockIdx.x * blockDim.x + threadIdx.x;
    if (i >= E) return;
    int is64 = g_is64;
    int s = (int)edge_at(ei, i, is64);
    int d = (int)edge_at(ei, E + i, is64);
    int pos = atomicAdd(&cur[d], 1);
    colA[pos] = s;
}

// ---------------------------------------------------------------------------
__device__ __forceinline__ uint32_t f2tf(float x) {
    uint32_t u;
    asm("cvt.rna.tf32.f32 %0, %1;" : "=r"(u) : "f"(x));
    return u;
}

// ---------------------------------------------------------------------------
// GEMM1: 128x256 block tile, BK=16, 256 threads (8 warps, 2x4), warp 64x64.
// Hs = (A @ B) * dinv[row].  Requires N % 256 == 0, K % 16 == 0. M guarded.
// Dynamic smem: As[2][16][136] + Bs[2][16][260] (uint32) = 50688 B.
// ---------------------------------------------------------------------------
#define G1_SMEM ((2*16*136 + 2*16*260) * 4)
#define AS(b,k,m) Asb[(((b)*16 + (k)) * 136) + (m)]
#define BS(b,k,nn) Bsb[(((b)*16 + (k)) * 260) + (nn)]

__global__ __launch_bounds__(256, 1)
void k_gemm256(const float* __restrict__ A, const float* __restrict__ B,
               const float* __restrict__ dinv, float* __restrict__ Hs,
               int M, int N, int K)
{
    extern __shared__ uint32_t smem_u[];
    uint32_t* Asb = smem_u;                 // [2][16][136]
    uint32_t* Bsb = smem_u + 2 * 16 * 136;  // [2][16][260]

    const int t    = threadIdx.x;
    const int lane = t & 31;
    const int wid  = t >> 5;
    const int wm   = wid >> 2;        // 0..1 (64 rows)
    const int wn   = wid & 3;         // 0..3 (64 cols)
    const int g    = lane >> 2;       // 0..7
    const int c    = lane & 3;        // 0..3
    const int m0   = blockIdx.y * 128;
    const int n0   = blockIdx.x * 256;

    const int arow = t >> 1;          // 0..127
    const int ak8  = (t & 1) * 8;     // 0 or 8
    const int bkr  = t >> 6;          // 0..3 (+4i)
    const int bn4  = t & 63;          // float4 col

    float acc[4][8][4];
#pragma unroll
    for (int i = 0; i < 4; i++)
#pragma unroll
        for (int j = 0; j < 8; j++)
#pragma unroll
            for (int q = 0; q < 4; q++) acc[i][j][q] = 0.0f;

    const int nt = K / 16;
    float4 ra[2], rb[4];

    // prologue loads (tile 0)
    {
        bool mv = (m0 + arow < M);
        ra[0] = mv ? *(const float4*)&A[(size_t)(m0 + arow) * K + ak8]     : make_float4(0,0,0,0);
        ra[1] = mv ? *(const float4*)&A[(size_t)(m0 + arow) * K + ak8 + 4] : make_float4(0,0,0,0);
#pragma unroll
        for (int i = 0; i < 4; i++)
            rb[i] = *(const float4*)&B[(size_t)(bkr + i * 4) * N + n0 + bn4 * 4];
    }
    // store tile 0 -> buf 0
    {
        const float* rap = (const float*)ra;
#pragma unroll
        for (int j = 0; j < 8; j++) AS(0, ak8 + j, arow) = f2tf(rap[j]);
#pragma unroll
        for (int i = 0; i < 4; i++) {
            int kr = bkr + i * 4;
            BS(0, kr, bn4 * 4 + 0) = f2tf(rb[i].x);
            BS(0, kr, bn4 * 4 + 1) = f2tf(rb[i].y);
            BS(0, kr, bn4 * 4 + 2) = f2tf(rb[i].z);
            BS(0, kr, bn4 * 4 + 3) = f2tf(rb[i].w);
        }
    }

    for (int tt = 0; tt < nt; tt++) {
        __syncthreads();
        const int buf = tt & 1;

        if (tt + 1 < nt) {
            int k0 = (tt + 1) * 16;
            bool mv = (m0 + arow < M);
            ra[0] = mv ? *(const float4*)&A[(size_t)(m0 + arow) * K + k0 + ak8]     : make_float4(0,0,0,0);
            ra[1] = mv ? *(const float4*)&A[(size_t)(m0 + arow) * K + k0 + ak8 + 4] : make_float4(0,0,0,0);
#pragma unroll
            for (int i = 0; i < 4; i++)
                rb[i] = *(const float4*)&B[(size_t)(k0 + bkr + i * 4) * N + n0 + bn4 * 4];
        }

#pragma unroll
        for (int kk = 0; kk < 2; kk++) {
            uint32_t af[4][4];
            uint32_t bf[8][2];
            const int kb = kk * 8;
#pragma unroll
            for (int fm = 0; fm < 4; fm++) {
                int mm = wm * 64 + fm * 16 + g;
                af[fm][0] = AS(buf, kb + c,     mm);
                af[fm][1] = AS(buf, kb + c,     mm + 8);
                af[fm][2] = AS(buf, kb + c + 4, mm);
                af[fm][3] = AS(buf, kb + c + 4, mm + 8);
            }
#pragma unroll
            for (int fn = 0; fn < 8; fn++) {
                int nn = wn * 64 + fn * 8 + g;
                bf[fn][0] = BS(buf, kb + c,     nn);
                bf[fn][1] = BS(buf, kb + c + 4, nn);
            }
#pragma unroll
            for (int fm = 0; fm < 4; fm++)
#pragma unroll
                for (int fn = 0; fn < 8; fn++) {
                    asm volatile(
                        "mma.sync.aligned.m16n8k8.row.col.f32.tf32.tf32.f32 "
                        "{%0,%1,%2,%3}, {%4,%5,%6,%7}, {%8,%9}, {%0,%1,%2,%3};"
                        : "+f"(acc[fm][fn][0]), "+f"(acc[fm][fn][1]),
                          "+f"(acc[fm][fn][2]), "+f"(acc[fm][fn][3])
                        : "r"(af[fm][0]), "r"(af[fm][1]), "r"(af[fm][2]), "r"(af[fm][3]),
                          "r"(bf[fn][0]), "r"(bf[fn][1]));
                }
        }

        if (tt + 1 < nt) {
            const int nbuf = 1 - buf;
            const float* rap = (const float*)ra;
#pragma unroll
            for (int j = 0; j < 8; j++) AS(nbuf, ak8 + j, arow) = f2tf(rap[j]);
#pragma unroll
            for (int i = 0; i < 4; i++) {
                int kr = bkr + i * 4;
                BS(nbuf, kr, bn4 * 4 + 0) = f2tf(rb[i].x);
                BS(nbuf, kr, bn4 * 4 + 1) = f2tf(rb[i].y);
                BS(nbuf, kr, bn4 * 4 + 2) = f2tf(rb[i].z);
                BS(nbuf, kr, bn4 * 4 + 3) = f2tf(rb[i].w);
            }
        }
    }

    // epilogue: scale rows by dinv, store
#pragma unroll
    for (int fm = 0; fm < 4; fm++) {
        int r0 = m0 + wm * 64 + fm * 16 + g;
        int r1 = r0 + 8;
        float d0 = (r0 < M) ? dinv[r0] : 0.0f;
        float d1 = (r1 < M) ? dinv[r1] : 0.0f;
#pragma unroll
        for (int fn = 0; fn < 8; fn++) {
            int col = n0 + wn * 64 + fn * 8 + c * 2;
            if (r0 < M) {
                float2 v = make_float2(acc[fm][fn][0] * d0, acc[fm][fn][1] * d0);
                *(float2*)&Hs[(size_t)r0 * N + col] = v;
            }
            if (r1 < M) {
                float2 v = make_float2(acc[fm][fn][2] * d1, acc[fm][fn][3] * d1);
                *(float2*)&Hs[(size_t)r1 * N + col] = v;
            }
        }
    }
}

// ---------------------------------------------------------------------------
// GEMM2 (proven R3 kernel): 128x128 block, warp 32x64, BK=16, static smem.
// ---------------------------------------------------------------------------
__global__ __launch_bounds__(256, 2)
void k_gemm_tf32(const float* __restrict__ A, const float* __restrict__ B,
                 const float* __restrict__ dinv, float* __restrict__ Hs,
                 int M, int N, int K)
{
    __shared__ uint32_t As[2][16][136];
    __shared__ uint32_t Bs[2][16][136];

    const int t    = threadIdx.x;
    const int lane = t & 31;
    const int wid  = t >> 5;
    const int wm   = wid >> 1;
    const int wn   = wid & 1;
    const int g    = lane >> 2;
    const int c    = lane & 3;
    const int m0   = blockIdx.y * 128;
    const int n0   = blockIdx.x * 128;

    const int arow = t >> 2;
    const int ac4  = t & 3;
    const int bkr  = t >> 5;
    const int bn4  = t & 31;

    float acc[2][8][4];
#pragma unroll
    for (int i = 0; i < 2; i++)
#pragma unroll
        for (int j = 0; j < 8; j++)
#pragma unroll
            for (int q = 0; q < 4; q++) acc[i][j][q] = 0.0f;

    const int nt = K / 16;
    float4 ra[2], rb[2];

#pragma unroll
    for (int it = 0; it < 2; it++) {
        int row = arow + it * 64;
        ra[it] = (m0 + row < M) ? *(const float4*)&A[(size_t)(m0 + row) * K + ac4 * 4]
                                : make_float4(0.f, 0.f, 0.f, 0.f);
        rb[it] = *(const float4*)&B[(size_t)(bkr + it * 8) * N + n0 + bn4 * 4];
    }
#pragma unroll
    for (int it = 0; it < 2; it++) {
        int row = arow + it * 64;
        As[0][ac4 * 4 + 0][row] = f2tf(ra[it].x);
        As[0][ac4 * 4 + 1][row] = f2tf(ra[it].y);
        As[0][ac4 * 4 + 2][row] = f2tf(ra[it].z);
        As[0][ac4 * 4 + 3][row] = f2tf(ra[it].w);
        int kr = bkr + it * 8;
        Bs[0][kr][bn4 * 4 + 0] = f2tf(rb[it].x);
        Bs[0][kr][bn4 * 4 + 1] = f2tf(rb[it].y);
        Bs[0][kr][bn4 * 4 + 2] = f2tf(rb[it].z);
        Bs[0][kr][bn4 * 4 + 3] = f2tf(rb[it].w);
    }

    for (int tt = 0; tt < nt; tt++) {
        __syncthreads();
        const int buf = tt & 1;

        if (tt + 1 < nt) {
            int k0 = (tt + 1) * 16;
#pragma unroll
            for (int it = 0; it < 2; it++) {
                int row = arow + it * 64;
                ra[it] = (m0 + row < M) ? *(const float4*)&A[(size_t)(m0 + row) * K + k0 + ac4 * 4]
                                        : make_float4(0.f, 0.f, 0.f, 0.f);
                rb[it] = *(const float4*)&B[(size_t)(k0 + bkr + it * 8) * N + n0 + bn4 * 4];
            }
        }

#pragma unroll
        for (int kk = 0; kk < 2; kk++) {
            uint32_t af[2][4];
            uint32_t bf[8][2];
            const int kb = kk * 8;
#pragma unroll
            for (int fm = 0; fm < 2; fm++) {
                int mm = wm * 32 + fm * 16 + g;
                af[fm][0] = As[buf][kb + c][mm];
                af[fm][1] = As[buf][kb + c][mm + 8];
                af[fm][2] = As[buf][kb + c + 4][mm];
                af[fm][3] = As[buf][kb + c + 4][mm + 8];
            }
#pragma unroll
            for (int fn = 0; fn < 8; fn++) {
                int nn = wn * 64 + fn * 8 + g;
                bf[fn][0] = Bs[buf][kb + c][nn];
                bf[fn][1] = Bs[buf][kb + c + 4][nn];
            }
#pragma unroll
            for (int fm = 0; fm < 2; fm++)
#pragma unroll
                for (int fn = 0; fn < 8; fn++) {
                    asm volatile(
                        "mma.sync.aligned.m16n8k8.row.col.f32.tf32.tf32.f32 "
                        "{%0,%1,%2,%3}, {%4,%5,%6,%7}, {%8,%9}, {%0,%1,%2,%3};"
                        : "+f"(acc[fm][fn][0]), "+f"(acc[fm][fn][1]),
                          "+f"(acc[fm][fn][2]), "+f"(acc[fm][fn][3])
                        : "r"(af[fm][0]), "r"(af[fm][1]), "r"(af[fm][2]), "r"(af[fm][3]),
                          "r"(bf[fn][0]), "r"(bf[fn][1]));
                }
        }

        if (tt + 1 < nt) {
            const int nbuf = 1 - buf;
#pragma unroll
            for (int it = 0; it < 2; it++) {
                int row = arow + it * 64;
                As[nbuf][ac4 * 4 + 0][row] = f2tf(ra[it].x);
                As[nbuf][ac4 * 4 + 1][row] = f2tf(ra[it].y);
                As[nbuf][ac4 * 4 + 2][row] = f2tf(ra[it].z);
                As[nbuf][ac4 * 4 + 3][row] = f2tf(ra[it].w);
                int kr = bkr + it * 8;
                Bs[nbuf][kr][bn4 * 4 + 0] = f2tf(rb[it].x);
                Bs[nbuf][kr][bn4 * 4 + 1] = f2tf(rb[it].y);
                Bs[nbuf][kr][bn4 * 4 + 2] = f2tf(rb[it].z);
                Bs[nbuf][kr][bn4 * 4 + 3] = f2tf(rb[it].w);
            }
        }
    }

#pragma unroll
    for (int fm = 0; fm < 2; fm++) {
        int r0 = m0 + wm * 32 + fm * 16 + g;
        int r1 = r0 + 8;
        float d0 = (r0 < M) ? dinv[r0] : 0.0f;
        float d1 = (r1 < M) ? dinv[r1] : 0.0f;
#pragma unroll
        for (int fn = 0; fn < 8; fn++) {
            int col = n0 + wn * 64 + fn * 8 + c * 2;
            if (r0 < M) {
                float2 v = make_float2(acc[fm][fn][0] * d0, acc[fm][fn][1] * d0);
                *(float2*)&Hs[(size_t)r0 * N + col] = v;
            }
            if (r1 < M) {
                float2 v = make_float2(acc[fm][fn][2] * d1, acc[fm][fn][3] * d1);
                *(float2*)&Hs[(size_t)r1 * N + col] = v;
            }
        }
    }
}

// ---------------------------------------------------------------------------
// pull aggregation, feature-chunked for L2 residency of the gather source.
// out[i, fbase..fbase+F4C) = b + dinv[i]*(hs[i] + sum_{e in row i} hs[col[e]])
// ---------------------------------------------------------------------------
template <int F4TOT, int F4C>
__global__ void k_pull_c(const int* __restrict__ rowp, const int* __restrict__ colA,
                         const float* __restrict__ hs, const float* __restrict__ dinv,
                         const float* __restrict__ bias, float* __restrict__ out,
                         int n, int fbase) {
    int idx = blockIdx.x * blockDim.x + threadIdx.x;
    int dst = idx / F4C;
    int j   = idx % F4C;
    if (dst >= n) return;
    int f4 = fbase + j;
    const float4* h4 = (const float4*)hs;
    float4 acc = h4[(size_t)dst * F4TOT + f4];   // self loop (hs already *dinv[src])
    int e0 = __ldg(&rowp[dst]);
    int e1 = __ldg(&rowp[dst + 1]);
    for (int e = e0; e < e1; e++) {
        int s = __ldg(&colA[e]);
        float4 v = h4[(size_t)s * F4TOT + f4];
        acc.x += v.x; acc.y += v.y; acc.z += v.z; acc.w += v.w;
    }
    float d = dinv[dst];
    float4 bb = ((const float4*)bias)[f4];
    float4 o = make_float4(bb.x + acc.x * d, bb.y + acc.y * d,
                           bb.z + acc.z * d, bb.w + acc.w * d);
    __stcs(&((float4*)out)[(size_t)dst * F4TOT + f4], o);
}

// ---------------------------------------------------------------------------
extern "C" void kernel_launch(void* const* d_in, const int* in_sizes, int n_in,
                              void* d_out, int out_size) {
    const float* x   = (const float*)d_in[0];
    const void*  ei  = d_in[1];
    const float* W1  = (const float*)d_in[3];
    const float* b1  = (const float*)d_in[4];
    const float* W2  = (const float*)d_in[5];
    const float* b2  = (const float*)d_in[6];
    float*       out = (float*)d_out;

    const long long nelem = (long long)in_sizes[1];
    const long long E     = nelem / 2;
    const int dhid        = in_sizes[4];         // 512
    const int dout        = in_sizes[6];         // 128
    const int din         = in_sizes[3] / dhid;  // 512
    const int n           = in_sizes[0] / din;   // 100000

    float *dinv_p, *h_p, *agg_p;
    int *cnt_p, *rowp_p, *cur_p, *col_p, *bsum_p;
    cudaGetSymbolAddress((void**)&dinv_p, g_dinv);
    cudaGetSymbolAddress((void**)&h_p,    g_h);
    cudaGetSymbolAddress((void**)&agg_p,  g_agg);
    cudaGetSymbolAddress((void**)&cnt_p,  g_cnt);
    cudaGetSymbolAddress((void**)&rowp_p, g_rowp);
    cudaGetSymbolAddress((void**)&cur_p,  g_cur);
    cudaGetSymbolAddress((void**)&col_p,  g_col);
    cudaGetSymbolAddress((void**)&bsum_p, g_bsum);

    static bool attr_set = false;
    if (!attr_set) {
        cudaFuncSetAttribute(k_gemm256, cudaFuncAttributeMaxDynamicSharedMemorySize, G1_SMEM);
        attr_set = true;
    }

    const int eb = (int)((E + 255) / 256);
    const int nb = (n + 255) / 256;
    const int nblk = (n + 1023) / 1024;

    // --- CSR build + dinv ---
    k_detect<<<1, 32>>>(ei, nelem, n);
    k_zero_cnt<<<nb, 256>>>(cnt_p, n);
    k_hist<<<eb, 256>>>(ei, E, cnt_p);
    k_scan_blk<<<nblk, 1024>>>(cnt_p, rowp_p, bsum_p, n);
    k_scan_top<<<1, 1024>>>(bsum_p, nblk);
    k_scan_add<<<(n + 256) / 256, 256>>>(rowp_p, bsum_p, n, nblk);
    k_dinv_cursor<<<nb, 256>>>(cnt_p, rowp_p, dinv_p, cur_p, n);
    k_scatter<<<eb, 256>>>(ei, E, cur_p, col_p);

    // --- layer 1 ---
    {
        dim3 grid(dhid / 256, (n + 127) / 128);
        k_gemm256<<<grid, 256, G1_SMEM>>>(x, W1, dinv_p, h_p, n, dhid, din);
        // chunked pull: 4 passes of 32 float4 (128 floats) each -> 51 MB L2 working set
        int tot = n * 32;
        for (int cidx = 0; cidx < 4; cidx++) {
            k_pull_c<128, 32><<<(tot + 255) / 256, 256>>>(rowp_p, col_p, h_p, dinv_p,
                                                          b1, agg_p, n, cidx * 32);
        }
    }

    // --- layer 2 ---
    {
        dim3 grid(dout / 128, (n + 127) / 128);
        k_gemm_tf32<<<grid, 256>>>(agg_p, W2, dinv_p, h_p, n, dout, dhid);
        int tot = n * 32;
        k_pull_c<32, 32><<<(tot + 255) / 256, 256>>>(rowp_p, col_p, h_p, dinv_p,
                                                     b2, out, n, 0);
    }

    (void)n_in; (void)out_size;
}